// round 3
// baseline (speedup 1.0000x reference)
#include <cuda_runtime.h>
#include <cstdint>
#include <cstddef>

#define BATCH   32
#define PRIORS  32768
#define NUMC    21
#define NCLS    20
#define NMSK    1000
#define TOPK    200
#define CONF_T  0.01f
#define NMS_T   0.3f
#define NT      256
#define CAP     2047          // gather cap (sort buffer 2048)

__device__ float  g_conf_t[(size_t)BATCH * NCLS * PRIORS];   // [b][c][p]
__device__ float4 g_decoded[(size_t)BATCH * PRIORS];

// ---------------------------------------------------------------------------
// Kernel 1: decode boxes + transpose conf
// ---------------------------------------------------------------------------
__global__ void prep_kernel(const float* __restrict__ loc,
                            const float* __restrict__ conf,
                            const float* __restrict__ prior) {
    int idx = blockIdx.x * blockDim.x + threadIdx.x;
    if (idx >= BATCH * PRIORS) return;
    int b = idx >> 15;
    int p = idx & (PRIORS - 1);

    float4 l  = reinterpret_cast<const float4*>(loc)[idx];
    float4 pr = reinterpret_cast<const float4*>(prior)[p];

    float cx = pr.x + (l.x * 0.1f) * pr.z;
    float cy = pr.y + (l.y * 0.1f) * pr.w;
    float w  = pr.z * expf(l.z * 0.2f);
    float h  = pr.w * expf(l.w * 0.2f);
    float x1 = cx - w * 0.5f;
    float y1 = cy - h * 0.5f;
    g_decoded[idx] = make_float4(x1, y1, x1 + w, y1 + h);

    const float* crow = conf + (size_t)idx * NUMC;
    size_t base = ((size_t)b * NCLS) << 15;
#pragma unroll
    for (int c = 0; c < NCLS; ++c)
        g_conf_t[base + ((size_t)c << 15) + p] = crow[c + 1];
}

// masked bit pattern: 0 if below conf threshold
__device__ __forceinline__ unsigned int maskbits(float v) {
    return (v > CONF_T) ? __float_as_uint(v) : 0u;
}

// ---------------------------------------------------------------------------
// Kernel 2: per (batch,class) exact top-1000 + greedy NMS + output
// ---------------------------------------------------------------------------
__global__ __launch_bounds__(NT) void nms_kernel(float* __restrict__ out) {
    int bx  = blockIdx.x;
    int b   = bx / NUMC;
    int cc  = bx % NUMC;
    int tid = threadIdx.x;
    float* outp = out + (size_t)bx * (TOPK * 5);

    if (cc == 0) {
        for (int i = tid; i < TOPK * 5; i += NT) outp[i] = 0.f;
        return;
    }
    int cls = cc - 1;
    const float* scrow = g_conf_t + (((size_t)b * NCLS + cls) << 15);
    const float4* sc4  = reinterpret_cast<const float4*>(scrow);

    // ---- shared arena (overlaid) ----
    __shared__ __align__(16) unsigned long long s_keys[2048];   // 16KB
    __shared__ __align__(16) unsigned char s_arena[20480];      // 20KB: samp | box+val
    __shared__ unsigned int s_thr[8];
    __shared__ int s_cnt[9];
    __shared__ unsigned int s_sup[32];
    __shared__ int s_keep[TOPK];
    __shared__ int s_scal[4];          // 0: gather count, 1: chosen T, 2: done flag

    unsigned int* s_samp = reinterpret_cast<unsigned int*>(s_arena);   // 1KB, early
    float4*       s_box  = reinterpret_cast<float4*>(s_arena);         // 16KB, late
    float*        s_val  = reinterpret_cast<float*>(s_arena + 16384);  // 4KB, late

    const unsigned int FULL = 0xffffffffu;
    const int lane = tid & 31;
    const int wid  = tid >> 5;

    // ---- Phase 0: sample 256 values, bitonic-sort descending ----
    s_samp[tid] = maskbits(scrow[tid << 7]);
    for (int k2 = 2; k2 <= 256; k2 <<= 1) {
        for (int j = k2 >> 1; j > 0; j >>= 1) {
            __syncthreads();
            int l = tid ^ j;
            if (l > tid) {
                unsigned int a = s_samp[tid], bb = s_samp[l];
                bool up = ((tid & k2) == 0);
                if (up ? (a < bb) : (a > bb)) { s_samp[tid] = bb; s_samp[l] = a; }
            }
        }
    }
    __syncthreads();
    // thresholds at sample ranks 2,4,6,8,11,14,17,20 (descending value)
    if (tid == 0) {
        const int rk[8] = {1, 3, 5, 7, 10, 13, 16, 19};
#pragma unroll
        for (int i = 0; i < 8; ++i) {
            unsigned int t = s_samp[rk[i]];
            s_thr[i] = t ? t : 1u;     // never 0 (0 would count non-pass elems)
        }
        s_scal[2] = 0;
    }

    // ---- Phase 1: threshold-count scan(s), atomics-free counting ----
    unsigned int Tstar = 1u;
#pragma unroll 1
    for (int round = 0; round < 4; ++round) {
        if (tid < 9) s_cnt[tid] = 0;
        __syncthreads();
        unsigned int T0 = s_thr[0], T1 = s_thr[1], T2 = s_thr[2], T3 = s_thr[3];
        unsigned int T4 = s_thr[4], T5 = s_thr[5], T6 = s_thr[6], T7 = s_thr[7];
        int c0 = 0, c1 = 0, c2 = 0, c3 = 0, c4 = 0, c5 = 0, c6 = 0, c7 = 0, c8 = 0;
        for (int i = tid; i < PRIORS / 4; i += NT) {
            float4 v = sc4[i];
            float vv[4] = {v.x, v.y, v.z, v.w};
#pragma unroll
            for (int c = 0; c < 4; ++c) {
                unsigned int bits = maskbits(vv[c]);
                c0 += (bits >= T0); c1 += (bits >= T1);
                c2 += (bits >= T2); c3 += (bits >= T3);
                c4 += (bits >= T4); c5 += (bits >= T5);
                c6 += (bits >= T6); c7 += (bits >= T7);
                c8 += (bits != 0u);
            }
        }
        int cc9[9] = {c0, c1, c2, c3, c4, c5, c6, c7, c8};
#pragma unroll
        for (int q = 0; q < 9; ++q) {
            int s = cc9[q];
#pragma unroll
            for (int o = 16; o; o >>= 1) s += __shfl_down_sync(FULL, s, o);
            if (lane == 0) atomicAdd(&s_cnt[q], s);
        }
        __syncthreads();
        if (tid == 0) {
            int call = s_cnt[8];
            if (call <= CAP) { s_scal[1] = 1; s_scal[2] = 1; }   // gather everything
            else {
                int sel = -1;
#pragma unroll
                for (int i = 0; i < 8; ++i)
                    if (s_cnt[i] >= NMSK) { sel = i; break; }
                if (sel >= 0 && s_cnt[sel] <= CAP) {
                    s_scal[1] = (int)s_thr[sel]; s_scal[2] = 1;
                } else {
                    unsigned int lo, hi;
                    if (sel >= 0) { lo = s_thr[sel]; hi = (sel > 0) ? s_thr[sel - 1] : 0x7F800000u; }
                    else          { lo = 1u;         hi = s_thr[7]; }
                    if (hi - lo < 16u) { s_scal[1] = (int)lo; s_scal[2] = 1; }  // degenerate
                    else {
                        unsigned long long span = (unsigned long long)(hi - lo);
#pragma unroll
                        for (int j = 0; j < 8; ++j)
                            s_thr[j] = lo + (unsigned int)(span * (8 - j) / 9);
                    }
                }
            }
        }
        __syncthreads();
        if (s_scal[2]) { Tstar = (unsigned int)s_scal[1]; break; }
        if (round == 3) Tstar = s_thr[7];   // last resort: smallest tried
    }

    // ---- Phase 2: gather candidates >= Tstar, pad to 2048 ----
    if (tid == 0) s_scal[0] = 0;
    for (int i = tid; i < 2048; i += NT) s_keys[i] = 0ull;
    __syncthreads();
    for (int i = tid; i < PRIORS / 4; i += NT) {
        float4 v = sc4[i];
        float vv[4] = {v.x, v.y, v.z, v.w};
#pragma unroll
        for (int c = 0; c < 4; ++c) {
            unsigned int bits = maskbits(vv[c]);
            if (bits >= Tstar) {
                int pos = atomicAdd(&s_scal[0], 1);
                if (pos <= CAP) {
                    unsigned int p = (unsigned int)(i * 4 + c);
                    s_keys[pos] = ((unsigned long long)bits << 32)
                                | (unsigned long long)(0xFFFFFFFFu - p);
                }
            }
        }
    }
    __syncthreads();

    // ---- Phase 3: bitonic sort 2048 keys descending ----
    for (int k2 = 2; k2 <= 2048; k2 <<= 1) {
        for (int j = k2 >> 1; j > 0; j >>= 1) {
            __syncthreads();
            for (int i = tid; i < 2048; i += NT) {
                int l = i ^ j;
                if (l > i) {
                    unsigned long long a = s_keys[i], bb = s_keys[l];
                    bool up = ((i & k2) == 0);
                    if (up ? (a < bb) : (a > bb)) { s_keys[i] = bb; s_keys[l] = a; }
                }
            }
        }
    }
    __syncthreads();

    // ---- Phase 4: extract top-1000 boxes into s_box/s_val (arena reuse) ----
    const float4* dec = g_decoded + ((size_t)b << 15);
    for (int r = tid; r < NMSK; r += NT) {
        unsigned long long key = s_keys[r];
        unsigned int bits = (unsigned int)(key >> 32);
        float v = __uint_as_float(bits);
        float4 bxv = make_float4(0.f, 0.f, 0.f, 0.f);
        if (v > CONF_T) {
            unsigned int p = 0xFFFFFFFFu - (unsigned int)(key & 0xFFFFFFFFull);
            bxv = dec[p];
        } else v = 0.f;
        s_box[r] = bxv;
        s_val[r] = v;
    }
    if (tid < 32) s_sup[tid] = 0u;
    __syncthreads();

    // ---- Phase 5: greedy NMS, one barrier per kept candidate ----
    int nkeep = 0;
    for (int k = 0; k < NMSK; ++k) {
        float vk = s_val[k];
        if (vk <= CONF_T) break;
        bool sup = (s_sup[k >> 5] >> (k & 31)) & 1u;
        if (!sup) {
            if (tid == 0) s_keep[nkeep] = k;
            nkeep++;
            if (nkeep >= TOPK) break;
            float4 bk = s_box[k];
            float ka = (bk.z - bk.x) * (bk.w - bk.y);
            for (int j = k + 1 + tid; j < NMSK; j += NT) {
                float4 bj = s_box[j];
                float aj = (bj.z - bj.x) * (bj.w - bj.y);
                float w = fminf(bj.z, bk.z) - fmaxf(bj.x, bk.x);
                float h = fminf(bj.w, bk.w) - fmaxf(bj.y, bk.y);
                w = fmaxf(w, 0.f); h = fmaxf(h, 0.f);
                float inter = w * h;
                float iou = inter / (aj + ka - inter);
                if (iou > NMS_T) atomicOr(&s_sup[j >> 5], 1u << (j & 31));
            }
            __syncthreads();
        }
    }
    __syncthreads();

    // ---- Phase 6: write output ----
    for (int r = tid; r < TOPK; r += NT) {
        float e0 = 0.f, e1 = 0.f, e2 = 0.f, e3 = 0.f, e4 = 0.f;
        if (r < nkeep) {
            int k = s_keep[r];
            float4 bk = s_box[k];
            e0 = s_val[k]; e1 = bk.x; e2 = bk.y; e3 = bk.z; e4 = bk.w;
        }
        float* row = outp + r * 5;
        row[0] = e0; row[1] = e1; row[2] = e2; row[3] = e3; row[4] = e4;
    }
}

// ---------------------------------------------------------------------------
extern "C" void kernel_launch(void* const* d_in, const int* in_sizes, int n_in,
                              void* d_out, int out_size) {
    const float *loc = nullptr, *conf = nullptr, *prior = nullptr;
    for (int i = 0; i < n_in; ++i) {
        long long sz = in_sizes[i];
        if      (sz == (long long)BATCH * PRIORS * 4)    loc   = (const float*)d_in[i];
        else if (sz == (long long)BATCH * PRIORS * NUMC) conf  = (const float*)d_in[i];
        else if (sz == (long long)PRIORS * 4)            prior = (const float*)d_in[i];
    }
    prep_kernel<<<(BATCH * PRIORS + 255) / 256, 256>>>(loc, conf, prior);
    nms_kernel<<<BATCH * NUMC, NT>>>((float*)d_out);
    (void)out_size;
}

// round 4
// speedup vs baseline: 1.0073x; 1.0073x over previous
#include <cuda_runtime.h>
#include <cstdint>
#include <cstddef>

#define BATCH   32
#define PRIORS  32768
#define NUMC    21
#define NCLS    20
#define NMSK    1000
#define TOPK    200
#define CONF_T  0.01f
#define NMS_T   0.3f
#define NT      256
#define T0F     0.95f

typedef unsigned long long ull;

__device__ float  g_conf_t[(size_t)BATCH * NCLS * PRIORS];   // [b][c][p]
__device__ float4 g_decoded[(size_t)BATCH * PRIORS];

// ---------------------------------------------------------------------------
// Kernel 1: decode boxes + transpose conf
// ---------------------------------------------------------------------------
__global__ void prep_kernel(const float* __restrict__ loc,
                            const float* __restrict__ conf,
                            const float* __restrict__ prior) {
    int idx = blockIdx.x * blockDim.x + threadIdx.x;
    if (idx >= BATCH * PRIORS) return;
    int b = idx >> 15;
    int p = idx & (PRIORS - 1);

    float4 l  = reinterpret_cast<const float4*>(loc)[idx];
    float4 pr = reinterpret_cast<const float4*>(prior)[p];

    float cx = pr.x + (l.x * 0.1f) * pr.z;
    float cy = pr.y + (l.y * 0.1f) * pr.w;
    float w  = pr.z * expf(l.z * 0.2f);
    float h  = pr.w * expf(l.w * 0.2f);
    float x1 = cx - w * 0.5f;
    float y1 = cy - h * 0.5f;
    g_decoded[idx] = make_float4(x1, y1, x1 + w, y1 + h);

    const float* crow = conf + (size_t)idx * NUMC;
    size_t base = ((size_t)b * NCLS) << 15;
#pragma unroll
    for (int c = 0; c < NCLS; ++c)
        g_conf_t[base + ((size_t)c << 15) + p] = crow[c + 1];
}

// ---------------------------------------------------------------------------
// Kernel 2: per (batch,class) exact top-1000 + windowed greedy NMS + output
// ---------------------------------------------------------------------------
__global__ __launch_bounds__(NT) void nms_kernel(float* __restrict__ out) {
    const int bx = blockIdx.x, b = bx / NUMC, cc = bx % NUMC;
    const int tid = threadIdx.x;
    float* outp = out + (size_t)bx * (TOPK * 5);

    if (cc == 0) {
        for (int i = tid; i < TOPK * 5; i += NT) outp[i] = 0.f;
        return;
    }
    const float* scrow = g_conf_t + (((size_t)b * NCLS + (cc - 1)) << 15);
    const float4* sc4  = reinterpret_cast<const float4*>(scrow);

    // 28KB overlaid arena
    __shared__ __align__(16) unsigned char s_mem[28672];
    ull*    s_keys = reinterpret_cast<ull*>(s_mem);            // [0,16K) 2048 keys
    ull*    s_dst  = reinterpret_cast<ull*>(s_mem + 16384);    // [16K,24K) 1024 keys
    int*    s_hist = reinterpret_cast<int*>(s_mem);            // fallback 4096 bins
    float4* s_box  = reinterpret_cast<float4*>(s_mem);         // [0,16K) late
    float*  s_val  = reinterpret_cast<float*>(s_mem + 24576);  // [24K,28K) late
    __shared__ int s_shist[256];
    __shared__ int s_win[32];
    __shared__ float4 s_wbox[32];
    __shared__ float s_warea[32];
    __shared__ unsigned int s_sup[32];
    __shared__ int s_keep[TOPK];
    __shared__ int s_cnt, s_clow, s_pivch, s_pivkk, s_pivbin, s_selb, s_sab, s_pc;
    __shared__ unsigned int s_umax;
    __shared__ int s_nwin, s_cursor, s_nkeep, s_stop;

    const unsigned int FULL = 0xffffffffu;
    const int lane = tid & 31;
    const int wid  = tid >> 5;

    // ---------- Phase A: one-scan gather at fast threshold ----------
    if (tid == 0) { s_cnt = 0; s_clow = 0; s_umax = 0u; }
    __syncthreads();
    unsigned int Tgt = __float_as_uint(T0F);          // gather bits > Tgt
    {
        int clow = 0; unsigned int um = 0u;
        for (int i = tid; i < PRIORS / 4; i += NT) {
            float4 v = sc4[i];
            float vv[4] = {v.x, v.y, v.z, v.w};
#pragma unroll
            for (int c = 0; c < 4; ++c) {
                float x = vv[c];
                unsigned int bits = __float_as_uint(x);
                if (x > CONF_T) {
                    if (bits > Tgt) {
                        int pos = atomicAdd(&s_cnt, 1);
                        if (pos < 2048) {
                            unsigned int p = (unsigned int)(i * 4 + c);
                            s_keys[pos] = ((ull)bits << 32) | (ull)(0xFFFFFFFFu - p);
                        }
                        um = um > bits ? um : bits;
                    } else clow++;
                }
            }
        }
#pragma unroll
        for (int o = 16; o; o >>= 1) {
            clow += __shfl_down_sync(FULL, clow, o);
            unsigned int t = __shfl_down_sync(FULL, um, o);
            um = um > t ? um : t;
        }
        if (lane == 0) { atomicAdd(&s_clow, clow); atomicMax(&s_umax, um); }
    }
    __syncthreads();
    int cnt = s_cnt;
    bool need_fb = (cnt > 2047) || (cnt < NMSK && s_clow > 0);

    // ---------- Fallback: exact 12-bit histogram pivot + re-gather (rare) ----------
    if (need_fb) {
        for (int i = tid; i < 4096; i += NT) s_hist[i] = 0;
        if (tid == 0) s_pivch = -1;
        __syncthreads();
        for (int i = tid; i < PRIORS / 4; i += NT) {
            float4 v = sc4[i];
            float vv[4] = {v.x, v.y, v.z, v.w};
#pragma unroll
            for (int c = 0; c < 4; ++c) {
                unsigned int bits = (vv[c] > CONF_T) ? __float_as_uint(vv[c]) : 0u;
                atomicAdd(&s_hist[bits >> 20], 1);
            }
        }
        __syncthreads();
        { int cs = 0; for (int j = 0; j < 16; ++j) cs += s_hist[tid * 16 + j]; s_shist[tid] = cs; }
        __syncthreads();
        for (int d = 1; d < 256; d <<= 1) {
            int v = (tid + d < 256) ? s_shist[tid + d] : 0;
            __syncthreads();
            s_shist[tid] += v;
            __syncthreads();
        }
        { int suf = s_shist[tid]; int sufn = (tid < 255) ? s_shist[tid + 1] : 0;
          if (suf >= NMSK && sufn < NMSK) { s_pivch = tid; s_pivkk = NMSK - sufn; } }
        __syncthreads();
        if (tid == 0) {
            int pb = 1;
            if (s_pivch >= 0) {
                int ch = s_pivch, kk = s_pivkk, run = 0;
                for (int j = 15; j >= 0; --j) {
                    run += s_hist[ch * 16 + j];
                    if (run >= kk) { pb = ch * 16 + j; break; }
                }
            }
            if (pb < 1) pb = 1;
            s_pivbin = pb;
            s_cnt = 0; s_umax = 0u;
        }
        __syncthreads();
        Tgt = (((unsigned int)s_pivbin) << 20) - 1u;
        {
            unsigned int um = 0u;
            for (int i = tid; i < PRIORS / 4; i += NT) {
                float4 v = sc4[i];
                float vv[4] = {v.x, v.y, v.z, v.w};
#pragma unroll
                for (int c = 0; c < 4; ++c) {
                    float x = vv[c];
                    unsigned int bits = __float_as_uint(x);
                    if (x > CONF_T && bits > Tgt) {
                        int pos = atomicAdd(&s_cnt, 1);
                        if (pos < 2048) {
                            unsigned int p = (unsigned int)(i * 4 + c);
                            s_keys[pos] = ((ull)bits << 32) | (ull)(0xFFFFFFFFu - p);
                        }
                        um = um > bits ? um : bits;
                    }
                }
            }
#pragma unroll
            for (int o = 16; o; o >>= 1) {
                unsigned int t = __shfl_down_sync(FULL, um, o);
                um = um > t ? um : t;
            }
            if (lane == 0) atomicMax(&s_umax, um);
        }
        __syncthreads();
        cnt = s_cnt; if (cnt > 2047) cnt = 2047;
    }

    // ---------- Phase B: refine to <=1024, sort ----------
    bool sorted2048 = false;
    int sabove = cnt;
    if (cnt > 1024) {
        unsigned int base = Tgt;                // gathered bits >= base+1
        unsigned int span = s_umax - base;
        int nbits = 32 - __clz((int)span);
        int shift = nbits > 8 ? nbits - 8 : 0;
        s_shist[tid] = 0;
        if (tid == 0) s_selb = -1;
        __syncthreads();
        for (int i = tid; i < cnt; i += NT) {
            unsigned int bits = (unsigned int)(s_keys[i] >> 32);
            atomicAdd(&s_shist[(bits - base) >> shift], 1);
        }
        __syncthreads();
        if (wid == 0) {
            int base8 = lane * 8;
            int h[8]; int s = 0;
#pragma unroll
            for (int j = 0; j < 8; ++j) { h[j] = s_shist[base8 + j]; s += h[j]; }
            int suf = s;
#pragma unroll
            for (int o = 1; o < 32; o <<= 1) {
                int t = __shfl_down_sync(FULL, suf, o);
                if (lane + o < 32) suf += t;
            }
            int sufn = __shfl_down_sync(FULL, suf, 1);
            if (lane == 31) sufn = 0;
            if (suf >= NMSK && sufn < NMSK) {
                int run = 0;
#pragma unroll
                for (int j = 7; j >= 0; --j) {
                    run += h[j];
                    if (sufn + run >= NMSK) { s_selb = base8 + j; s_sab = sufn + run; break; }
                }
            }
        }
        __syncthreads();
        int selb = s_selb;
        if (selb >= 0 && s_sab <= 1024) {
            unsigned int T2 = base + (((unsigned int)selb) << shift);
            if (tid == 0) s_pc = 0;
            for (int i = tid; i < 1024; i += NT) s_dst[i] = 0ull;
            __syncthreads();
            for (int i = tid; i < cnt; i += NT) {
                ull k = s_keys[i];
                if ((unsigned int)(k >> 32) >= T2) {
                    int p = atomicAdd(&s_pc, 1);
                    if (p < 1024) s_dst[p] = k;
                }
            }
            sabove = s_sab;
        } else {
            // rare: sort 2048 in place, copy top-1000 to s_dst
            for (int i = cnt + tid; i < 2048; i += NT) s_keys[i] = 0ull;
            for (int k2 = 2; k2 <= 2048; k2 <<= 1) {
                for (int j = k2 >> 1; j > 0; j >>= 1) {
                    __syncthreads();
                    for (int i = tid; i < 2048; i += NT) {
                        int l = i ^ j;
                        if (l > i) {
                            ull a = s_keys[i], bb = s_keys[l];
                            bool up = ((i & k2) == 0);
                            if (up ? (a < bb) : (a > bb)) { s_keys[i] = bb; s_keys[l] = a; }
                        }
                    }
                }
            }
            __syncthreads();
            for (int i = tid; i < 1024; i += NT) s_dst[i] = (i < NMSK) ? s_keys[i] : 0ull;
            sorted2048 = true;
        }
    } else {
        for (int i = tid; i < 1024; i += NT) s_dst[i] = (i < cnt) ? s_keys[i] : 0ull;
    }
    __syncthreads();
    if (!sorted2048) {
        // bitonic sort 1024 descending; warp-sync for in-warp strides
        for (int k2 = 2; k2 <= 1024; k2 <<= 1) {
            for (int j = k2 >> 1; j > 0; j >>= 1) {
                if (j >= 16) __syncthreads(); else __syncwarp();
                for (int i = tid; i < 1024; i += NT) {
                    int l = i ^ j;
                    if (l > i) {
                        ull a = s_dst[i], bb = s_dst[l];
                        bool up = ((i & k2) == 0);
                        if (up ? (a < bb) : (a > bb)) { s_dst[i] = bb; s_dst[l] = a; }
                    }
                }
            }
        }
        __syncthreads();
    }

    // ---------- Phase C: extract boxes (s_box aliases dead s_keys) ----------
    const float4* dec = g_decoded + ((size_t)b << 15);
    const int nvalid = sabove < NMSK ? sabove : NMSK;
    for (int r = tid; r < 1024; r += NT) {
        float v = 0.f;
        float4 bb = make_float4(0.f, 0.f, 0.f, 0.f);
        if (r < NMSK) {
            ull key = s_dst[r];
            unsigned int bits = (unsigned int)(key >> 32);
            v = __uint_as_float(bits);
            if (v > CONF_T) {
                unsigned int p = 0xFFFFFFFFu - (unsigned int)(key & 0xFFFFFFFFull);
                bb = dec[p];
            } else v = 0.f;
        }
        s_box[r] = bb;
        s_val[r] = v;
    }
    if (tid < 32) s_sup[tid] = 0u;
    if (tid == 0) { s_cursor = 0; s_nkeep = 0; s_stop = 0; }
    __syncthreads();

    // ---------- Phase D: windowed greedy NMS (32 leaders per round) ----------
    while (true) {
        // collect next <=32 unsuppressed candidates (warp 0)
        if (wid == 0) {
            int k0 = s_cursor;
            int bw = k0 >> 5;
            int wi = bw + lane;
            unsigned int wm = 0u;
            if (wi < 32) {
                wm = ~s_sup[wi];
                if (wi == bw) wm &= (0xffffffffu << (k0 & 31));
                int hi = nvalid - wi * 32;
                if (hi <= 0) wm = 0u;
                else if (hi < 32) wm &= (1u << hi) - 1u;
            }
            int c = __popc(wm);
            int ex = c;
#pragma unroll
            for (int o = 1; o < 32; o <<= 1) {
                int t = __shfl_up_sync(FULL, ex, o);
                if (lane >= o) ex += t;
            }
            int excl = ex - c;
            unsigned int m = wm; int pos = excl;
            while (m && pos < 32) {
                int bit = __ffs(m) - 1;
                s_win[pos] = wi * 32 + bit;
                m &= m - 1; ++pos;
            }
            int total = __shfl_sync(FULL, ex, 31);
            if (lane == 0) s_nwin = total < 32 ? total : 32;
        }
        __syncthreads();
        int nwin = s_nwin;
        if (nwin == 0) break;
        if (tid < nwin) {
            int k = s_win[tid];
            float4 bk = s_box[k];
            s_wbox[tid] = bk;
            s_warea[tid] = (bk.z - bk.x) * (bk.w - bk.y);
        }
        __syncthreads();
        int wlast = s_win[nwin - 1];
        int nkeep0 = s_nkeep;

        // intra-window IoU (each warp redundantly; lane a vs b>a)
        unsigned int sup_a = 0u;
        if (lane < nwin) {
            float4 ba = s_wbox[lane];
            float aa = s_warea[lane];
            for (int b2 = lane + 1; b2 < nwin; ++b2) {
                float4 bb = s_wbox[b2];
                float w = fminf(bb.z, ba.z) - fmaxf(bb.x, ba.x);
                float h = fminf(bb.w, ba.w) - fmaxf(bb.y, ba.y);
                w = fmaxf(w, 0.f); h = fmaxf(h, 0.f);
                float inter = w * h;
                if (inter / (s_warea[b2] + aa - inter) > NMS_T) sup_a |= (1u << b2);
            }
        }
        // replay greedy chain in-warp (identical in every warp)
        unsigned int kept = 0u, csup = 0u;
        int nk = 0, cap = TOPK - nkeep0;
        for (int a = 0; a < nwin; ++a) {
            unsigned int sa = __shfl_sync(FULL, sup_a, a);
            if (!((csup >> a) & 1u)) {
                if (nk >= cap) break;
                kept |= 1u << a; ++nk; csup |= sa;
            }
        }

        // suppress remaining candidates vs kept window members
        for (int j = wlast + 1 + tid; j < nvalid; j += NT) {
            if ((s_sup[j >> 5] >> (j & 31)) & 1u) continue;
            float4 bj = s_box[j];
            float aj = (bj.z - bj.x) * (bj.w - bj.y);
            unsigned int m = kept;
            while (m) {
                int a = __ffs(m) - 1; m &= m - 1;
                float4 ba = s_wbox[a];
                float w = fminf(bj.z, ba.z) - fmaxf(bj.x, ba.x);
                float h = fminf(bj.w, ba.w) - fmaxf(bj.y, ba.y);
                w = fmaxf(w, 0.f); h = fmaxf(h, 0.f);
                float inter = w * h;
                if (inter / (aj + s_warea[a] - inter) > NMS_T) {
                    atomicOr(&s_sup[j >> 5], 1u << (j & 31));
                    break;
                }
            }
        }
        __syncthreads();
        if (tid == 0) {
            unsigned int m = kept;
            int nkp = s_nkeep;
            while (m) { int a = __ffs(m) - 1; m &= m - 1; s_keep[nkp++] = s_win[a]; }
            s_nkeep = nkp;
            s_cursor = wlast + 1;
            s_stop = (nkp >= TOPK) ? 1 : 0;
        }
        __syncthreads();
        if (s_stop) break;
    }
    __syncthreads();

    // ---------- Phase E: write output ----------
    int nkeep = s_nkeep;
    for (int r = tid; r < TOPK; r += NT) {
        float e0 = 0.f, e1 = 0.f, e2 = 0.f, e3 = 0.f, e4 = 0.f;
        if (r < nkeep) {
            int k = s_keep[r];
            float4 bk = s_box[k];
            e0 = s_val[k]; e1 = bk.x; e2 = bk.y; e3 = bk.z; e4 = bk.w;
        }
        float* row = outp + r * 5;
        row[0] = e0; row[1] = e1; row[2] = e2; row[3] = e3; row[4] = e4;
    }
}

// ---------------------------------------------------------------------------
extern "C" void kernel_launch(void* const* d_in, const int* in_sizes, int n_in,
                              void* d_out, int out_size) {
    const float *loc = nullptr, *conf = nullptr, *prior = nullptr;
    for (int i = 0; i < n_in; ++i) {
        long long sz = in_sizes[i];
        if      (sz == (long long)BATCH * PRIORS * 4)    loc   = (const float*)d_in[i];
        else if (sz == (long long)BATCH * PRIORS * NUMC) conf  = (const float*)d_in[i];
        else if (sz == (long long)PRIORS * 4)            prior = (const float*)d_in[i];
    }
    prep_kernel<<<(BATCH * PRIORS + 255) / 256, 256>>>(loc, conf, prior);
    nms_kernel<<<BATCH * NUMC, NT>>>((float*)d_out);
    (void)out_size;
}